// round 3
// baseline (speedup 1.0000x reference)
#include <cuda_runtime.h>

// LIF_21260088115614 — fused smooth + GEMM + LIF scan, fp32.
//
// Bit-matching strategy vs the JAX/XLA fp32 reference:
//   - smoothing: ascending-tap FFMA chain (matches cuDNN direct conv)
//   - GEMM: strictly sequential c=0..255 single-accumulator FFMA
//     (matches cublas/cutlass SIMT sgemm k-order)
//   - LIF scan: NON-contracted mul+add via __fmul_rn/__fadd_rn
//     (XLA elemental emitter does not fuse fmul+fadd into fma)
//
// inputs: d_in[0] = inputs (2048, 100, 256) f32
//         d_in[1] = w      (256, 256)       f32
//         d_in[2] = epsilon (5,)            f32
// output: d_out = [mem_rec (2048,100,256) | spk_rec (2048,100,256)] f32

#define T_STEPS 100
#define C_DIM   256
#define SAMPLE_ELEMS (T_STEPS * C_DIM)   // 25600

// fp32 roundings of exp(-1e-3/0.005), exp(-1e-3/0.01) — matches JAX weak-typed
// Python-float scalars entering f32 ops.
#define ALPHA_F 0.81873075307798182f
#define BETA_F  0.90483741803595952f

__global__ void __launch_bounds__(256, 1)
lif_fused_kernel(const float* __restrict__ in,
                 const float* __restrict__ w,
                 const float* __restrict__ eps,
                 float* __restrict__ out_mem,
                 float* __restrict__ out_spk)
{
    extern __shared__ float smem[];
    float* xs  = smem;                 // smoothed inputs, [t][c], 25600 floats
    float* buf = smem + SAMPLE_ELEMS;  // raw inputs, later h1, 25600 floats

    const int tid = threadIdx.x;       // 0..255
    const int n   = blockIdx.x;

    // ---- 1. load raw sample into smem (float4, fully coalesced) ----
    {
        const float4* in4  = reinterpret_cast<const float4*>(in + (size_t)n * SAMPLE_ELEMS);
        float4*       buf4 = reinterpret_cast<float4*>(buf);
        #pragma unroll
        for (int i = 0; i < 25; ++i)
            buf4[tid + i * 256] = in4[tid + i * 256];
    }
    const float e0 = eps[0], e1 = eps[1], e2 = eps[2], e3 = eps[3], e4 = eps[4];
    __syncthreads();

    // ---- 2. temporal smoothing: thread = channel c, ascending-tap FFMA chain ----
    {
        const int c = tid;
        float xm2 = 0.0f, xm1 = 0.0f;
        float x0  = buf[0 * C_DIM + c];
        float xp1 = buf[1 * C_DIM + c];
        #pragma unroll 4
        for (int t = 0; t < T_STEPS; ++t) {
            float xp2 = (t + 2 < T_STEPS) ? buf[(t + 2) * C_DIM + c] : 0.0f;
            float s = __fmul_rn(e0, xm2);
            s = __fmaf_rn(e1, xm1, s);
            s = __fmaf_rn(e2, x0,  s);
            s = __fmaf_rn(e3, xp1, s);
            s = __fmaf_rn(e4, xp2, s);
            xs[t * C_DIM + c] = s;
            xm2 = xm1; xm1 = x0; x0 = xp1; xp1 = xp2;
        }
    }
    __syncthreads();

    // ---- 3. GEMM h1[t][d] = sum_c xs[t][c] * w[c][d] ----
    // sequential c=0..255 single-accumulator FFMA (matches SIMT sgemm)
    // thread (tr = tid>>6, dg = tid&63) owns t = tr*25 + [0,25), d = dg*4 + [0,4)
    const int tr = tid >> 6;
    const int dg = tid & 63;

    float acc[25][4];
    #pragma unroll
    for (int i = 0; i < 25; ++i) {
        acc[i][0] = 0.0f; acc[i][1] = 0.0f; acc[i][2] = 0.0f; acc[i][3] = 0.0f;
    }

    const float4* w4  = reinterpret_cast<const float4*>(w);   // row c = 64 float4
    const float*  xsr = xs + tr * 25 * C_DIM;

    for (int c = 0; c < C_DIM; ++c) {
        const float4 wv = __ldg(&w4[c * 64 + dg]);   // w[c][4d..4d+3]
        float xv[25];
        #pragma unroll
        for (int i = 0; i < 25; ++i)
            xv[i] = xsr[i * C_DIM + c];              // warp-broadcast LDS
        #pragma unroll
        for (int i = 0; i < 25; ++i) {
            acc[i][0] = __fmaf_rn(xv[i], wv.x, acc[i][0]);
            acc[i][1] = __fmaf_rn(xv[i], wv.y, acc[i][1]);
            acc[i][2] = __fmaf_rn(xv[i], wv.z, acc[i][2]);
            acc[i][3] = __fmaf_rn(xv[i], wv.w, acc[i][3]);
        }
    }

    __syncthreads();

    // ---- 4. stage h1 into buf (raw data dead since step 2) ----
    {
        float4* h14 = reinterpret_cast<float4*>(buf);
        #pragma unroll
        for (int i = 0; i < 25; ++i)
            h14[(tr * 25 + i) * 64 + dg] =
                make_float4(acc[i][0], acc[i][1], acc[i][2], acc[i][3]);
    }
    __syncthreads();

    // ---- 5. LIF scan: thread = output channel d = tid ----
    // NON-contracted mul+add, replicating XLA's separate fmul/fadd roundings.
    {
        float syn = 0.0f, mem = 0.0f;
        float* om = out_mem + (size_t)n * SAMPLE_ELEMS;
        float* os = out_spk + (size_t)n * SAMPLE_ELEMS;
        #pragma unroll 4
        for (int t = 0; t < T_STEPS; ++t) {
            const float h   = buf[t * C_DIM + tid];
            const float spk = (__fadd_rn(mem, -1.0f) > 0.0f) ? 1.0f : 0.0f;
            om[t * C_DIM + tid] = mem;                      // carry-in mem
            os[t * C_DIM + tid] = spk;
            // new_syn = ALPHA*syn + h      (two roundings)
            const float nsyn = __fadd_rn(__fmul_rn(ALPHA_F, syn), h);
            // new_mem = (BETA*mem + syn) * (1 - spk)   (two roundings + exact mul)
            const float bm   = __fadd_rn(__fmul_rn(BETA_F, mem), syn);
            mem = __fmul_rn(bm, __fadd_rn(1.0f, -spk));
            syn = nsyn;
        }
    }
}

extern "C" void kernel_launch(void* const* d_in, const int* in_sizes, int n_in,
                              void* d_out, int out_size)
{
    const float* in  = (const float*)d_in[0];
    const float* w   = (const float*)d_in[1];
    const float* eps = (const float*)d_in[2];
    float* out = (float*)d_out;
    const int half = out_size / 2;   // mem_rec first, then spk_rec

    const int smem_bytes = 2 * SAMPLE_ELEMS * (int)sizeof(float);  // 204800
    cudaFuncSetAttribute(lif_fused_kernel,
                         cudaFuncAttributeMaxDynamicSharedMemorySize, smem_bytes);

    lif_fused_kernel<<<2048, 256, smem_bytes>>>(in, w, eps, out, out + half);
}

// round 5
// speedup vs baseline: 1.7980x; 1.7980x over previous
#include <cuda_runtime.h>

// LIF_21260088115614 — fused smooth + GEMM + LIF scan, fp32, FFMA2 (f32x2) GEMM.
//
// Bit-identical to the round-3 passing kernel (rel_err margin is thin):
//   - smoothing: same ascending-tap FFMA chain, same order
//   - GEMM: same strictly-sequential c=0..255 single-accumulator chains;
//     fma.rn.f32x2 lanes are IEEE-rn fp32 FMAs == scalar __fmaf_rn bit-for-bit.
//     Packing is over t-PAIRS: xs stored transposed [c][t] so ld.shared.b64
//     yields (x_t, x_t+1) packed for free; w broadcast-packed (w,w) 4x per c.
//   - LIF scan: same non-contracted __fmul_rn/__fadd_rn sequence.
//
// inputs: d_in[0] = inputs (2048, 100, 256) f32
//         d_in[1] = w      (256, 256)       f32
//         d_in[2] = epsilon (5,)            f32
// output: d_out = [mem_rec (2048,100,256) | spk_rec (2048,100,256)] f32

#define T_STEPS 100
#define T_PAD   102        // even (b64 align for even t), stride 102%32=6 -> only 2-way on smooth writes
#define C_DIM   256
#define SAMPLE_ELEMS (T_STEPS * C_DIM)        // 25600
#define XS_ELEMS     (C_DIM * T_PAD)          // 26112

#define ALPHA_F 0.81873075307798182f
#define BETA_F  0.90483741803595952f

__device__ __forceinline__ unsigned long long pack2(float lo_and_hi)
{
    unsigned long long r;
    asm("mov.b64 %0, {%1, %1};" : "=l"(r) : "f"(lo_and_hi));
    return r;
}

__device__ __forceinline__ void ffma2(unsigned long long& acc,
                                      unsigned long long a,
                                      unsigned long long b)
{
    asm("fma.rn.f32x2 %0, %1, %2, %0;" : "+l"(acc) : "l"(a), "l"(b));
}

__global__ void __launch_bounds__(256, 1)
lif_fused_kernel(const float* __restrict__ in,
                 const float* __restrict__ w,
                 const float* __restrict__ eps,
                 float* __restrict__ out_mem,
                 float* __restrict__ out_spk)
{
    extern __shared__ float smem[];
    float* xs  = smem;             // smoothed, TRANSPOSED [c][T_PAD]
    float* buf = smem + XS_ELEMS;  // raw inputs [t][c], later h1 [t][d]

    const int tid = threadIdx.x;   // 0..255
    const int n   = blockIdx.x;

    // ---- 1. load raw sample into smem (float4, fully coalesced) ----
    {
        const float4* in4  = reinterpret_cast<const float4*>(in + (size_t)n * SAMPLE_ELEMS);
        float4*       buf4 = reinterpret_cast<float4*>(buf);
        #pragma unroll
        for (int i = 0; i < 25; ++i)
            buf4[tid + i * 256] = in4[tid + i * 256];
    }
    const float e0 = eps[0], e1 = eps[1], e2 = eps[2], e3 = eps[3], e4 = eps[4];
    __syncthreads();

    // ---- 2. temporal smoothing: thread = channel c; write TRANSPOSED xs[c][t] ----
    {
        const int c = tid;
        float* xrow = xs + c * T_PAD;
        float xm2 = 0.0f, xm1 = 0.0f;
        float x0  = buf[0 * C_DIM + c];
        float xp1 = buf[1 * C_DIM + c];
        #pragma unroll 4
        for (int t = 0; t < T_STEPS; ++t) {
            float xp2 = (t + 2 < T_STEPS) ? buf[(t + 2) * C_DIM + c] : 0.0f;
            float s = __fmul_rn(e0, xm2);
            s = __fmaf_rn(e1, xm1, s);
            s = __fmaf_rn(e2, x0,  s);
            s = __fmaf_rn(e3, xp1, s);
            s = __fmaf_rn(e4, xp2, s);
            xrow[t] = s;
            xm2 = xm1; xm1 = x0; x0 = xp1; xp1 = xp2;
        }
    }
    __syncthreads();

    // ---- 3. GEMM h1[t][d] = sum_c xs_t[c][t] * w[c][d], FFMA2 over t-pairs ----
    // thread (tr = tid>>6, dg = tid&63) owns t = tr*25 + [0,25), d = dg*4 + [0,4)
    const int tr = tid >> 6;
    const int dg = tid & 63;
    const int t0 = tr * 25;
    const int odd = tr & 1;               // parity of t0
    const int pbase = t0 + odd;           // first paired t (even)
    const int sc_t  = odd ? t0 : t0 + 24; // leftover scalar t

    unsigned long long acc2[12][4];       // [t-pair][d], lo = earlier t
    float accS[4];
    #pragma unroll
    for (int j = 0; j < 12; ++j)
        #pragma unroll
        for (int d = 0; d < 4; ++d) acc2[j][d] = 0ull;
    accS[0] = accS[1] = accS[2] = accS[3] = 0.0f;

    const float4* w4 = reinterpret_cast<const float4*>(w);   // row c = 64 float4
    float4 wv = __ldg(&w4[dg]);                              // prefetch c=0

    #pragma unroll 2
    for (int c = 0; c < C_DIM; ++c) {
        const float4 wn = __ldg(&w4[((c + 1) & 255) * 64 + dg]);  // prefetch next

        const unsigned long long wx = pack2(wv.x);
        const unsigned long long wy = pack2(wv.y);
        const unsigned long long wz = pack2(wv.z);
        const unsigned long long ww = pack2(wv.w);

        const float* xrow = xs + c * T_PAD;
        const unsigned long long* xp =
            reinterpret_cast<const unsigned long long*>(xrow + pbase);
        const float xsc = xrow[sc_t];

        #pragma unroll
        for (int j = 0; j < 12; ++j) {
            const unsigned long long x2 = xp[j];   // broadcast LDS.64: (x_t, x_t+1)
            ffma2(acc2[j][0], x2, wx);
            ffma2(acc2[j][1], x2, wy);
            ffma2(acc2[j][2], x2, wz);
            ffma2(acc2[j][3], x2, ww);
        }
        accS[0] = __fmaf_rn(xsc, wv.x, accS[0]);
        accS[1] = __fmaf_rn(xsc, wv.y, accS[1]);
        accS[2] = __fmaf_rn(xsc, wv.z, accS[2]);
        accS[3] = __fmaf_rn(xsc, wv.w, accS[3]);

        wv = wn;
    }

    __syncthreads();

    // ---- 4. stage h1 into buf[t][d] ----
    {
        float4* h14 = reinterpret_cast<float4*>(buf);
        #pragma unroll
        for (int j = 0; j < 12; ++j) {
            const int tlo = pbase + 2 * j;
            float2 a0 = *reinterpret_cast<float2*>(&acc2[j][0]);
            float2 a1 = *reinterpret_cast<float2*>(&acc2[j][1]);
            float2 a2 = *reinterpret_cast<float2*>(&acc2[j][2]);
            float2 a3 = *reinterpret_cast<float2*>(&acc2[j][3]);
            h14[tlo * 64 + dg]       = make_float4(a0.x, a1.x, a2.x, a3.x);
            h14[(tlo + 1) * 64 + dg] = make_float4(a0.y, a1.y, a2.y, a3.y);
        }
        h14[sc_t * 64 + dg] = make_float4(accS[0], accS[1], accS[2], accS[3]);
    }
    __syncthreads();

    // ---- 5. LIF scan: thread = output channel d = tid ----
    // NON-contracted mul+add, replicating XLA's separate fmul/fadd roundings.
    {
        float syn = 0.0f, mem = 0.0f;
        float* om = out_mem + (size_t)n * SAMPLE_ELEMS;
        float* os = out_spk + (size_t)n * SAMPLE_ELEMS;
        #pragma unroll 4
        for (int t = 0; t < T_STEPS; ++t) {
            const float h   = buf[t * C_DIM + tid];
            const float spk = (__fadd_rn(mem, -1.0f) > 0.0f) ? 1.0f : 0.0f;
            om[t * C_DIM + tid] = mem;                      // carry-in mem
            os[t * C_DIM + tid] = spk;
            const float nsyn = __fadd_rn(__fmul_rn(ALPHA_F, syn), h);
            const float bm   = __fadd_rn(__fmul_rn(BETA_F, mem), syn);
            mem = __fmul_rn(bm, __fadd_rn(1.0f, -spk));
            syn = nsyn;
        }
    }
}

extern "C" void kernel_launch(void* const* d_in, const int* in_sizes, int n_in,
                              void* d_out, int out_size)
{
    const float* in  = (const float*)d_in[0];
    const float* w   = (const float*)d_in[1];
    const float* eps = (const float*)d_in[2];
    float* out = (float*)d_out;
    const int half = out_size / 2;   // mem_rec first, then spk_rec

    const int smem_bytes = (XS_ELEMS + SAMPLE_ELEMS) * (int)sizeof(float);  // 206848
    cudaFuncSetAttribute(lif_fused_kernel,
                         cudaFuncAttributeMaxDynamicSharedMemorySize, smem_bytes);

    lif_fused_kernel<<<2048, 256, smem_bytes>>>(in, w, eps, out, out + half);
}